// round 10
// baseline (speedup 1.0000x reference)
#include <cuda_runtime.h>
#include <cuda_bf16.h>
#include <math.h>
#include <stdint.h>

// ---------------------------------------------------------------------------
// DCN layer, all-tensor-pipe (mma.sync bf16 hi/lo 3-split), ldmatrix B loads:
//   k_prep       : weight fragment packing (deform + offconv)
//   k_prep_feat  : feat=concat(xf,xi) -> packed bf16 hi/lo (offconv input)
//   k_prep_xT    : input_feat -> channel-last fp32 [b][y][x][c] (deform gather)
//   k_offconv_mma: offset/mask conv, LDSM.x4 + XOR-swizzled slab
//   k_deform_mma : deformable conv, 2m x 4n warp tile + LDSM.x4
// B=4, Cin=64, Cout=128, H=W=128, K=9, stride=1, pad=1, dil=1
// ---------------------------------------------------------------------------

#define B_   4
#define C_   64
#define O_   128
#define H_   128
#define W_   128
#define HW_  (H_*W_)

// ---- scratch --------------------------------------------------------------
__device__ float g_om[B_ * H_ * W_ * 28];   // per-pixel [dy0,dx0,..,dy8,dx8,m0..m8]
// deform weights, A-frag layout: ((((tap*2+split)*4+ks)*8+wt)*32+lane)*4+reg
__device__ __align__(16) uint32_t g_wfrag[9 * 2 * 4 * 8 * 32 * 4];
// offconv weights, A-frag layout: ((((tap*2+split)*8+ks)*2+mi)*32+lane)*4+reg
__device__ __align__(16) uint32_t g_wofrag[9 * 2 * 8 * 2 * 32 * 4];
// feat bf16 hi/lo packed: [b][c(128)][y][x]
__device__ __align__(16) uint32_t g_fhl[B_ * 128 * HW_];
// input_feat channel-last fp32: [b][y][x][c=64]
__device__ __align__(16) float g_xT[(long)B_ * HW_ * C_];

// ---- helpers --------------------------------------------------------------
__device__ __forceinline__ void mma_bf16(float* d, const uint32_t* a,
                                         uint32_t b0, uint32_t b1) {
    asm("mma.sync.aligned.m16n8k16.row.col.f32.bf16.bf16.f32 "
        "{%0,%1,%2,%3}, {%4,%5,%6,%7}, {%8,%9}, {%0,%1,%2,%3};"
        : "+f"(d[0]), "+f"(d[1]), "+f"(d[2]), "+f"(d[3])
        : "r"(a[0]), "r"(a[1]), "r"(a[2]), "r"(a[3]), "r"(b0), "r"(b1));
}
__device__ __forceinline__ void ldsm4(uint32_t* f, uint32_t addr) {
    asm volatile("ldmatrix.sync.aligned.m8n8.x4.shared.b16 {%0,%1,%2,%3}, [%4];"
        : "=r"(f[0]), "=r"(f[1]), "=r"(f[2]), "=r"(f[3]) : "r"(addr));
}
__device__ __forceinline__ uint32_t bf16x2(float v0, float v1) {
    __nv_bfloat162 h;
    h.x = __float2bfloat16(v0);
    h.y = __float2bfloat16(v1);
    return *(uint32_t*)&h;
}
__device__ __forceinline__ uint32_t pack_hl(float v) {
    __nv_bfloat16 h = __float2bfloat16(v);
    __nv_bfloat16 l = __float2bfloat16(v - __bfloat162float(h));
    return (uint32_t)*(uint16_t*)&h | ((uint32_t)*(uint16_t*)&l << 16);
}

// ---------------------------------------------------------------------------
// Prep: weight fragment packing
// ---------------------------------------------------------------------------
__global__ void k_prep(const float* __restrict__ w, const float* __restrict__ w_om) {
    int i = blockIdx.x * blockDim.x + threadIdx.x;
    if (i < 9 * 2 * 4 * 8 * 32 * 4) {
        int reg  = i & 3;
        int lane = (i >> 2) & 31;
        int wt   = (i >> 7) & 7;
        int ks   = (i >> 10) & 3;
        int split= (i >> 12) & 1;
        int tap  = i >> 13;
        int gid = lane >> 2, tid4 = lane & 3;
        int row  = gid + ((reg & 1) ? 8 : 0);
        int colb = 2 * tid4 + ((reg & 2) ? 8 : 0);
        int o = wt * 16 + row;
        int c0 = ks * 16 + colb;
        float w0 = w[(o * C_ + c0) * 9 + tap];
        float w1 = w[(o * C_ + c0 + 1) * 9 + tap];
        __nv_bfloat16 h0 = __float2bfloat16(w0);
        __nv_bfloat16 h1 = __float2bfloat16(w1);
        float v0, v1;
        if (split == 0) { v0 = __bfloat162float(h0); v1 = __bfloat162float(h1); }
        else { v0 = w0 - __bfloat162float(h0); v1 = w1 - __bfloat162float(h1); }
        g_wfrag[i] = bf16x2(v0, v1);
    }
    if (i < 9 * 2 * 8 * 2 * 32 * 4) {
        int reg  = i & 3;
        int lane = (i >> 2) & 31;
        int mi   = (i >> 7) & 1;
        int ks   = (i >> 8) & 7;
        int split= (i >> 11) & 1;
        int tap  = i >> 12;
        int gid = lane >> 2, tid4 = lane & 3;
        int row  = gid + ((reg & 1) ? 8 : 0);
        int colb = 2 * tid4 + ((reg & 2) ? 8 : 0);
        int o = mi * 16 + row;
        int c0 = ks * 16 + colb;
        float w0 = 0.f, w1 = 0.f;
        if (o < 27) {
            w0 = w_om[(o * 128 + c0) * 9 + tap];
            w1 = w_om[(o * 128 + c0 + 1) * 9 + tap];
        }
        __nv_bfloat16 h0 = __float2bfloat16(w0);
        __nv_bfloat16 h1 = __float2bfloat16(w1);
        float v0, v1;
        if (split == 0) { v0 = __bfloat162float(h0); v1 = __bfloat162float(h1); }
        else { v0 = w0 - __bfloat162float(h0); v1 = w1 - __bfloat162float(h1); }
        g_wofrag[i] = bf16x2(v0, v1);
    }
}

// ---------------------------------------------------------------------------
// Prep: feat -> packed bf16 hi/lo (for offconv)
// ---------------------------------------------------------------------------
__global__ __launch_bounds__(256) void k_prep_feat(
    const float* __restrict__ xf, const float* __restrict__ xi)
{
    long base = ((long)blockIdx.x * 256 + threadIdx.x) * 4;
    int b = (int)(base >> 21);
    int c = (int)(base >> 14) & 127;
    int off = (int)base & 16383;
    const float* src = (c < C_) ? (xf + (((long)(b * C_ + c)) << 14) + off)
                                : (xi + (((long)(b * C_ + (c - C_))) << 14) + off);
    float4 v = *(const float4*)src;
    uint4 r;
    r.x = pack_hl(v.x); r.y = pack_hl(v.y);
    r.z = pack_hl(v.z); r.w = pack_hl(v.w);
    *(uint4*)&g_fhl[base] = r;
}

// ---------------------------------------------------------------------------
// Prep: input_feat -> channel-last fp32 (for deform gather).
// ---------------------------------------------------------------------------
__global__ __launch_bounds__(256) void k_prep_xT(const float* __restrict__ xf)
{
    __shared__ float sm[64][129];
    const int y = blockIdx.x;
    const int b = blockIdx.y;
    for (int i = threadIdx.x; i < 64 * 128; i += 256) {
        int c = i >> 7, p = i & 127;
        sm[c][p] = xf[(((long)(b * C_ + c)) << 14) + (y << 7) + p];
    }
    __syncthreads();
    float* dst = g_xT + ((((long)b << 7) + y) << 7) * 64;
    for (int i = threadIdx.x; i < 64 * 128; i += 256) {
        int p = i >> 6, c = i & 63;
        dst[(long)p * 64 + c] = sm[c][p];
    }
}

// ---------------------------------------------------------------------------
// Kernel 1: offset/mask conv via mma.sync + LDSM.x4.
// Slab rows XOR-swizzled in 16-elem groups: g -> g ^ ((row>>3)&3).
// VS2 = 136 elems (272B rows, 16B-aligned for ldmatrix).
// ---------------------------------------------------------------------------
#define VS2 136

__global__ __launch_bounds__(256, 2) void k_offconv_mma(
    const float* __restrict__ b_om)
{
    extern __shared__ __align__(16) __nv_bfloat16 osm[];
    __nv_bfloat16* vh = osm;                 // 130*VS2
    __nv_bfloat16* vl = osm + 130 * VS2;     // 130*VS2

    const int t    = threadIdx.x;
    const int lane = t & 31;
    const int wid  = t >> 5;
    const int gid  = lane >> 2;
    const int tid4 = lane & 3;
    const int y    = blockIdx.x;
    const int b    = blockIdx.y;

    const int mi = wid & 1;                  // m-tile
    const int nb = (wid >> 1) * 32;          // n base (32 px per warp pair)

    // ldmatrix lane base: matrices 0/1 from vh (k, k+8), 2/3 from vl
    const int lr = lane & 7, lm = lane >> 3;
    const uint32_t obase = (uint32_t)__cvta_generic_to_shared(osm)
        + (uint32_t)((lm >> 1) * (130 * VS2 * 2))
        + (uint32_t)((lm & 1) * 16);

    // zero pad rows 0 and 129 (swizzle-invariant: all zeros)
    if (t < VS2) {
        vh[t] = __nv_bfloat16(0.f);             vl[t] = __nv_bfloat16(0.f);
        vh[129 * VS2 + t] = __nv_bfloat16(0.f); vl[129 * VS2 + t] = __nv_bfloat16(0.f);
    }

    float acc[4][4];
#pragma unroll
    for (int nt = 0; nt < 4; nt++)
#pragma unroll
        for (int q = 0; q < 4; q++) acc[nt][q] = 0.f;

    for (int dy = 0; dy < 3; dy++) {
        __syncthreads();
        // --- gather+transpose slab for source row y+dy-1 (swizzled store) ---
        {
            const int p  = t & 127;
            const int ch = (t >> 7) * 64;
            const int r  = p + 1;
            const int key = (r >> 3) & 3;
            const int ysrc = y + dy - 1;
            uint32_t* rowh = (uint32_t*)&vh[r * VS2];
            uint32_t* rowl = (uint32_t*)&vl[r * VS2];
            if (ysrc >= 0 && ysrc < H_) {
                const uint32_t* s = g_fhl + (((long)(b * 128 + ch)) << 14) + (ysrc << 7) + p;
#pragma unroll 8
                for (int j = 0; j < 64; j += 2) {
                    uint32_t u0 = s[0];
                    uint32_t u1 = s[16384];
                    s += 32768;
                    int e  = ch + j;
                    int es = ((((e >> 4) ^ key) << 4) | (e & 15)) >> 1;
                    rowh[es] = (u0 & 0xffffu) | (u1 << 16);
                    rowl[es] = (u0 >> 16) | (u1 & 0xffff0000u);
                }
            } else {
                const int b0 = ch >> 1;
#pragma unroll
                for (int j = 0; j < 32; j++) { rowh[b0 + j] = 0u; rowl[b0 + j] = 0u; }
            }
        }
        __syncthreads();

        // --- 3 dx-taps on this slab ---
#pragma unroll
        for (int dx = 0; dx < 3; dx++) {
            const int tap = dy * 3 + dx;
            const uint32_t* wf_h = g_wofrag + ((((tap * 2 + 0) * 8) * 2 + mi) * 32 + lane) * 4;
            const uint32_t* wf_l = g_wofrag + ((((tap * 2 + 1) * 8) * 2 + mi) * 32 + lane) * 4;
#pragma unroll
            for (int ks = 0; ks < 8; ks++) {
                uint4 ahv = *(const uint4*)(wf_h + ks * (2 * 32 * 4));
                uint4 alv = *(const uint4*)(wf_l + ks * (2 * 32 * 4));
                uint32_t ah[4] = {ahv.x, ahv.y, ahv.z, ahv.w};
                uint32_t al[4] = {alv.x, alv.y, alv.z, alv.w};
#pragma unroll
                for (int nt = 0; nt < 4; nt++) {
                    const int r = nb + nt * 8 + dx + lr;         // slab row (per lane)
                    const uint32_t a = obase
                        + (uint32_t)(r * (VS2 * 2))
                        + (uint32_t)((ks ^ ((r >> 3) & 3)) << 5);
                    uint32_t bf[4];
                    ldsm4(bf, a);
                    mma_bf16(acc[nt], ah, bf[0], bf[1]);
                    mma_bf16(acc[nt], ah, bf[2], bf[3]);
                    mma_bf16(acc[nt], al, bf[0], bf[1]);
                }
            }
        }
    }

    // --- epilogue: +bias, sigmoid on mask rows, store to g_om ---
    const int r0 = mi * 16 + gid;
    const int r1 = r0 + 8;
    const float bo0 = b_om[r0];
    const float bo1 = (r1 < 27) ? b_om[r1] : 0.f;
    float* omb = g_om + ((long)((b * H_ + y) * W_)) * 28;
#pragma unroll
    for (int nt = 0; nt < 4; nt++) {
        const int p = nb + nt * 8 + 2 * tid4;
        float v0 = acc[nt][0] + bo0, v1 = acc[nt][1] + bo0;
        float v2 = acc[nt][2] + bo1, v3 = acc[nt][3] + bo1;
        if (r0 >= 18) { v0 = 1.f / (1.f + expf(-v0)); v1 = 1.f / (1.f + expf(-v1)); }
        if (r1 >= 18) { v2 = 1.f / (1.f + expf(-v2)); v3 = 1.f / (1.f + expf(-v3)); }
        omb[(long)p * 28 + r0]       = v0;
        omb[(long)(p + 1) * 28 + r0] = v1;
        if (r1 < 27) {
            omb[(long)p * 28 + r1]       = v2;
            omb[(long)(p + 1) * 28 + r1] = v3;
        }
    }
}

// ---------------------------------------------------------------------------
// Kernel 2: deformable conv. Warp tile 2m x 4n (64o x 32p each) + LDSM.x4:
// B-side SMEM traffic /4 vs 8x(16o x 128p). VSTRIDE=72 (144B) is 16B-aligned
// and conflict-free for both STS (consecutive lanes) and LDSM rows.
// ---------------------------------------------------------------------------
#define VSTRIDE 72

__global__ __launch_bounds__(256, 2) void k_deform_mma(
    const float* __restrict__ bias, float* __restrict__ out)
{
    __shared__ __align__(16) __nv_bfloat16 vsh[2][128 * VSTRIDE];
    __shared__ float cw[4][128];
    __shared__ int   cof[4][128];

    const int t    = threadIdx.x;
    const int lane = t & 31;
    const int wid  = t >> 5;
    const int gid  = lane >> 2;
    const int tid4 = lane & 3;
    const int y    = blockIdx.x;
    const int b    = blockIdx.y;
    const int mi   = wid & 1;               // o half: 0..63 / 64..127
    const int nj   = wid >> 1;              // px quarter: 32 px

    const int lr = lane & 7, lm = lane >> 3;
    const uint32_t vbase = (uint32_t)__cvta_generic_to_shared(&vsh[0][0])
        + (uint32_t)((lm >> 1) * (128 * VSTRIDE * 2))
        + (uint32_t)((lm & 1) * 16)
        + (uint32_t)(lr * (VSTRIDE * 2));

    const float2* xt = (const float2*)g_xT + ((long)b << 19);

    float acc[4][4][4];
#pragma unroll
    for (int mt = 0; mt < 4; mt++)
#pragma unroll
        for (int nt = 0; nt < 4; nt++)
#pragma unroll
            for (int q = 0; q < 4; q++) acc[mt][nt][q] = 0.f;

    for (int k = 0; k < 9; k++) {
        // --- per-pixel coords: clamped corners + mask-premultiplied weights ---
        if (t < 128) {
            const int p = t;
            const float* omp = g_om + ((long)((b * H_ + y) * W_) + p) * 28;
            float dy = omp[2 * k], dx = omp[2 * k + 1], m = omp[18 + k];
            float py  = (float)(y + k / 3 - 1) + dy;
            float pxf = (float)(p + k % 3 - 1) + dx;
            float fy = floorf(py), fx = floorf(pxf);
            int iy = (int)fy, ix = (int)fx;
            float wy = py - fy, wx = pxf - fx;
            int iy1 = iy + 1, ix1 = ix + 1;
            bool vy0 = (iy  >= 0) & (iy  < H_);
            bool vy1 = (iy1 >= 0) & (iy1 < H_);
            bool vx0 = (ix  >= 0) & (ix  < W_);
            bool vx1 = (ix1 >= 0) & (ix1 < W_);
            int cy0 = min(max(iy,  0), H_ - 1), cy1 = min(max(iy1, 0), H_ - 1);
            int cx0 = min(max(ix,  0), W_ - 1), cx1 = min(max(ix1, 0), W_ - 1);
            cof[0][p] = cy0 * W_ + cx0;
            cof[1][p] = cy0 * W_ + cx1;
            cof[2][p] = cy1 * W_ + cx0;
            cof[3][p] = cy1 * W_ + cx1;
            cw[0][p] = (vy0 & vx0) ? (1.f - wy) * (1.f - wx) * m : 0.f;
            cw[1][p] = (vy0 & vx1) ? (1.f - wy) * wx         * m : 0.f;
            cw[2][p] = (vy1 & vx0) ? wy         * (1.f - wx) * m : 0.f;
            cw[3][p] = (vy1 & vx1) ? wy         * wx         * m : 0.f;
        }
        __syncthreads();

        // --- gather: warp per 16-pixel group, lane = channel pair (LDG.64) ---
        {
            const int p0 = wid * 16;
#pragma unroll 4
            for (int pi = 0; pi < 16; pi++) {
                const int p = p0 + pi;
                const long a00 = (long)cof[0][p] * 32 + lane;
                const long a01 = (long)cof[1][p] * 32 + lane;
                const long a10 = (long)cof[2][p] * 32 + lane;
                const long a11 = (long)cof[3][p] * 32 + lane;
                const float w00 = cw[0][p], w01 = cw[1][p];
                const float w10 = cw[2][p], w11 = cw[3][p];
                float2 x00 = xt[a00];
                float2 x01 = xt[a01];
                float2 x10 = xt[a10];
                float2 x11 = xt[a11];
                float vx = fmaf(w00, x00.x, fmaf(w01, x01.x,
                           fmaf(w10, x10.x, w11 * x11.x)));
                float vy = fmaf(w00, x00.y, fmaf(w01, x01.y,
                           fmaf(w10, x10.y, w11 * x11.y)));
                __nv_bfloat16 h0 = __float2bfloat16(vx);
                __nv_bfloat16 h1 = __float2bfloat16(vy);
                float l0 = vx - __bfloat162float(h0);
                float l1 = vy - __bfloat162float(h1);
                __nv_bfloat162 hv; hv.x = h0; hv.y = h1;
                *(uint32_t*)&vsh[0][p * VSTRIDE + 2 * lane] = *(uint32_t*)&hv;
                *(uint32_t*)&vsh[1][p * VSTRIDE + 2 * lane] = bf16x2(l0, l1);
            }
        }
        __syncthreads();

        // --- mma: per ks load 4 B-frag quads (LDSM.x4), sweep 4 m-tiles ---
#pragma unroll
        for (int ks = 0; ks < 4; ks++) {
            uint32_t bf[4][4];
#pragma unroll
            for (int nt = 0; nt < 4; nt++)
                ldsm4(bf[nt], vbase +
                      (uint32_t)(((nj * 32 + nt * 8) * VSTRIDE + ks * 16) * 2));
#pragma unroll
            for (int mt = 0; mt < 4; mt++) {
                const int wt = mi * 4 + mt;
                const uint32_t* ph = g_wfrag + ((((k * 2 + 0) * 4 + ks) * 8 + wt) * 32 + lane) * 4;
                const uint32_t* pl = g_wfrag + ((((k * 2 + 1) * 4 + ks) * 8 + wt) * 32 + lane) * 4;
                uint4 ahv = *(const uint4*)ph;
                uint4 alv = *(const uint4*)pl;
                uint32_t ah[4] = {ahv.x, ahv.y, ahv.z, ahv.w};
                uint32_t al[4] = {alv.x, alv.y, alv.z, alv.w};
#pragma unroll
                for (int nt = 0; nt < 4; nt++) {
                    mma_bf16(acc[mt][nt], ah, bf[nt][0], bf[nt][1]);
                    mma_bf16(acc[mt][nt], ah, bf[nt][2], bf[nt][3]);
                    mma_bf16(acc[mt][nt], al, bf[nt][0], bf[nt][1]);
                }
            }
        }
        __syncthreads();
    }

    // --- epilogue: +bias, float2 stores ---
#pragma unroll
    for (int mt = 0; mt < 4; mt++) {
        const int o0 = mi * 64 + mt * 16 + gid;
        const int o1 = o0 + 8;
        const float bo0 = bias[o0];
        const float bo1 = bias[o1];
        float* r0 = out + (((long)(b * O_ + o0) * H_ + y) << 7);
        float* r1 = out + (((long)(b * O_ + o1) * H_ + y) << 7);
#pragma unroll
        for (int nt = 0; nt < 4; nt++) {
            const int p = nj * 32 + nt * 8 + 2 * tid4;
            *(float2*)(r0 + p) = make_float2(acc[mt][nt][0] + bo0, acc[mt][nt][1] + bo0);
            *(float2*)(r1 + p) = make_float2(acc[mt][nt][2] + bo1, acc[mt][nt][3] + bo1);
        }
    }
}

// ---------------------------------------------------------------------------
extern "C" void kernel_launch(void* const* d_in, const int* in_sizes, int n_in,
                              void* d_out, int out_size)
{
    const float* input_feat = (const float*)d_in[0];  // [4,64,128,128]
    const float* inter      = (const float*)d_in[1];  // [4,64,128,128]
    const float* weight     = (const float*)d_in[2];  // [128,64,3,3]
    const float* bias       = (const float*)d_in[3];  // [128]
    const float* w_om       = (const float*)d_in[4];  // [27,128,3,3]
    const float* b_om       = (const float*)d_in[5];  // [27]
    float* out = (float*)d_out;                       // [4,128,128,128]

    static int smem_set = 0;
    if (!smem_set) {
        cudaFuncSetAttribute(k_offconv_mma,
                             cudaFuncAttributeMaxDynamicSharedMemorySize,
                             2 * 130 * VS2 * (int)sizeof(__nv_bfloat16));
        smem_set = 1;
    }

    k_prep<<<288, 256>>>(weight, w_om);
    k_prep_feat<<<8192, 256>>>(input_feat, inter);
    k_prep_xT<<<dim3(128, 4), 256>>>(input_feat);
    k_offconv_mma<<<dim3(128, 4), 256,
                    2 * 130 * VS2 * sizeof(__nv_bfloat16)>>>(b_om);
    k_deform_mma<<<dim3(128, 4), 256>>>(bias, out);
}

// round 12
// speedup vs baseline: 1.4139x; 1.4139x over previous
#include <cuda_runtime.h>
#include <cuda_fp16.h>
#include <math.h>
#include <stdint.h>

// ---------------------------------------------------------------------------
// DCN layer via mma.sync fp16 2-split (A = hi+lo fp16, B = single fp16):
//   k_prep       : weight fragment packing (deform + offconv), fp16 hi/lo
//   k_prep_feat  : feat=concat(xf,xi) -> fp16 channel-pair packed u32
//   k_offconv_mma: offset/mask conv, 2-product mma
//   k_deform_mma : modulated deformable conv, 2-product mma
// Error model: dropped a*b_lo term, |b_lo| <= 2^-12 |b|  =>  rel err ~1.5e-4.
// B=4, Cin=64, Cout=128, H=W=128, K=9, stride=1, pad=1, dil=1
// ---------------------------------------------------------------------------

#define B_   4
#define C_   64
#define O_   128
#define H_   128
#define W_   128
#define HW_  (H_*W_)

// ---- scratch --------------------------------------------------------------
__device__ float g_om[B_ * H_ * W_ * 28];   // per-pixel [dy0,dx0,..,dy8,dx8,m0..m8]
// deform weights, A-frag: ((((tap*2+split)*4+ks)*8+wt)*32+lane)*4+reg  (u32=2 fp16)
__device__ __align__(16) uint32_t g_wfrag[9 * 2 * 4 * 8 * 32 * 4];
// offconv weights, A-frag: ((((tap*2+split)*8+ks)*2+mi)*32+lane)*4+reg
__device__ __align__(16) uint32_t g_wofrag[9 * 2 * 8 * 2 * 32 * 4];
// feat fp16, channel-pair packed: [b][c2=64][y][x], u32 = (fp16 c=2*c2, fp16 c=2*c2+1)
__device__ __align__(16) uint32_t g_fh2[B_ * 64 * HW_];

// ---- helpers --------------------------------------------------------------
__device__ __forceinline__ void mma_f16(float* d, const uint32_t* a,
                                        uint32_t b0, uint32_t b1) {
    asm("mma.sync.aligned.m16n8k16.row.col.f32.f16.f16.f32 "
        "{%0,%1,%2,%3}, {%4,%5,%6,%7}, {%8,%9}, {%0,%1,%2,%3};"
        : "+f"(d[0]), "+f"(d[1]), "+f"(d[2]), "+f"(d[3])
        : "r"(a[0]), "r"(a[1]), "r"(a[2]), "r"(a[3]), "r"(b0), "r"(b1));
}
__device__ __forceinline__ uint32_t f16x2(float v0, float v1) {
    __half2 h;
    h.x = __float2half(v0);
    h.y = __float2half(v1);
    return *(uint32_t*)&h;
}

// ---------------------------------------------------------------------------
// Prep: weight fragment packing (fp16 hi + fp16 residual)
// ---------------------------------------------------------------------------
__global__ void k_prep(const float* __restrict__ w, const float* __restrict__ w_om) {
    int i = blockIdx.x * blockDim.x + threadIdx.x;
    if (i < 9 * 2 * 4 * 8 * 32 * 4) {
        int reg  = i & 3;
        int lane = (i >> 2) & 31;
        int wt   = (i >> 7) & 7;
        int ks   = (i >> 10) & 3;
        int split= (i >> 12) & 1;
        int tap  = i >> 13;
        int gid = lane >> 2, tid4 = lane & 3;
        int row  = gid + ((reg & 1) ? 8 : 0);
        int colb = 2 * tid4 + ((reg & 2) ? 8 : 0);
        int o = wt * 16 + row;
        int c0 = ks * 16 + colb;
        float w0 = w[(o * C_ + c0) * 9 + tap];
        float w1 = w[(o * C_ + c0 + 1) * 9 + tap];
        float h0 = __half2float(__float2half(w0));
        float h1 = __half2float(__float2half(w1));
        g_wfrag[i] = (split == 0) ? f16x2(h0, h1) : f16x2(w0 - h0, w1 - h1);
    }
    if (i < 9 * 2 * 8 * 2 * 32 * 4) {
        int reg  = i & 3;
        int lane = (i >> 2) & 31;
        int mi   = (i >> 7) & 1;
        int ks   = (i >> 8) & 7;
        int split= (i >> 11) & 1;
        int tap  = i >> 12;
        int gid = lane >> 2, tid4 = lane & 3;
        int row  = gid + ((reg & 1) ? 8 : 0);
        int colb = 2 * tid4 + ((reg & 2) ? 8 : 0);
        int o = mi * 16 + row;
        int c0 = ks * 16 + colb;
        float w0 = 0.f, w1 = 0.f;
        if (o < 27) {
            w0 = w_om[(o * 128 + c0) * 9 + tap];
            w1 = w_om[(o * 128 + c0 + 1) * 9 + tap];
        }
        float h0 = __half2float(__float2half(w0));
        float h1 = __half2float(__float2half(w1));
        g_wofrag[i] = (split == 0) ? f16x2(h0, h1) : f16x2(w0 - h0, w1 - h1);
    }
}

// ---------------------------------------------------------------------------
// Prep: feat -> fp16 channel-pair packed (for offconv B tiles).
// 4096 blocks x 256 thr, 4 u32 per thread.
// ---------------------------------------------------------------------------
__global__ __launch_bounds__(256) void k_prep_feat(
    const float* __restrict__ xf, const float* __restrict__ xi)
{
    long base = ((long)blockIdx.x * 256 + threadIdx.x) * 4;  // u32 index
    int b   = (int)(base >> 20);
    int c2  = (int)(base >> 14) & 63;
    int off = (int)base & 16383;
    int c0 = 2 * c2, c1 = c0 + 1;
    const float* s0 = (c0 < C_) ? (xf + (((long)(b * C_ + c0)) << 14) + off)
                                : (xi + (((long)(b * C_ + c0 - C_)) << 14) + off);
    const float* s1 = (c1 < C_) ? (xf + (((long)(b * C_ + c1)) << 14) + off)
                                : (xi + (((long)(b * C_ + c1 - C_)) << 14) + off);
    float4 a = *(const float4*)s0;
    float4 c = *(const float4*)s1;
    uint4 r;
    r.x = f16x2(a.x, c.x); r.y = f16x2(a.y, c.y);
    r.z = f16x2(a.z, c.z); r.w = f16x2(a.w, c.w);
    *(uint4*)&g_fh2[base] = r;
}

// ---------------------------------------------------------------------------
// Kernel 1: offset/mask conv via mma.sync fp16 2-product.
// Block = one image row. D[32 o][128 p], K = 3 dy x 3 dx x 128 ch.
// Slab: [p+1][c] fp16, rows 0..129 (0,129 zero pad), VS2=134 (67 u32, odd).
// ---------------------------------------------------------------------------
#define VS2 134

__global__ __launch_bounds__(256, 2) void k_offconv_mma(
    const float* __restrict__ b_om)
{
    __shared__ __align__(16) __half vh[130 * VS2];

    const int t    = threadIdx.x;
    const int lane = t & 31;
    const int wid  = t >> 5;
    const int gid  = lane >> 2;
    const int tid4 = lane & 3;
    const int y    = blockIdx.x;
    const int b    = blockIdx.y;

    const int mi = wid & 1;                  // m-tile
    const int nb = (wid >> 1) * 32;          // n base (32 px per warp pair)

    uint32_t* vhu = (uint32_t*)vh;

    // zero pad rows 0 and 129
    if (t < VS2) {
        vh[t] = __float2half(0.f);
        vh[129 * VS2 + t] = __float2half(0.f);
    }

    float acc[4][4];
#pragma unroll
    for (int nt = 0; nt < 4; nt++)
#pragma unroll
        for (int q = 0; q < 4; q++) acc[nt][q] = 0.f;

    for (int dy = 0; dy < 3; dy++) {
        __syncthreads();
        // --- gather slab for source row y+dy-1: direct u32 channel pairs ---
        {
            const int p   = t & 127;
            const int c2b = (t >> 7) * 32;   // 32 channel-pairs per thread half
            const int ysrc = y + dy - 1;
            uint32_t* rowd = vhu + (p + 1) * (VS2 / 2) + c2b;
            if (ysrc >= 0 && ysrc < H_) {
                const uint32_t* s = g_fh2 + (((long)(b * 64 + c2b)) << 14) + (ysrc << 7) + p;
#pragma unroll 8
                for (int j = 0; j < 32; j++)
                    rowd[j] = s[(long)j << 14];
            } else {
#pragma unroll
                for (int j = 0; j < 32; j++) rowd[j] = 0u;
            }
        }
        __syncthreads();

        // --- 3 dx-taps on this slab, 2-product mma ---
#pragma unroll
        for (int dx = 0; dx < 3; dx++) {
            const int tap = dy * 3 + dx;
            const uint32_t* wf_h = g_wofrag + ((((tap * 2 + 0) * 8) * 2 + mi) * 32 + lane) * 4;
            const uint32_t* wf_l = g_wofrag + ((((tap * 2 + 1) * 8) * 2 + mi) * 32 + lane) * 4;
#pragma unroll
            for (int ks = 0; ks < 8; ks++) {
                uint4 ahv = *(const uint4*)(wf_h + ks * (2 * 32 * 4));
                uint4 alv = *(const uint4*)(wf_l + ks * (2 * 32 * 4));
                uint32_t ah[4] = {ahv.x, ahv.y, ahv.z, ahv.w};
                uint32_t al[4] = {alv.x, alv.y, alv.z, alv.w};
#pragma unroll
                for (int nt = 0; nt < 4; nt++) {
                    const int row = nb + nt * 8 + gid + dx;
                    const int ad = row * (VS2 / 2) + ks * 8 + tid4;
                    uint32_t b0 = vhu[ad];
                    uint32_t b1 = vhu[ad + 4];
                    mma_f16(acc[nt], ah, b0, b1);
                    mma_f16(acc[nt], al, b0, b1);
                }
            }
        }
    }

    // --- epilogue: +bias, sigmoid on mask rows, store to g_om ---
    const int r0 = mi * 16 + gid;
    const int r1 = r0 + 8;
    const float bo0 = b_om[r0];
    const float bo1 = (r1 < 27) ? b_om[r1] : 0.f;
    float* omb = g_om + ((long)((b * H_ + y) * W_)) * 28;
#pragma unroll
    for (int nt = 0; nt < 4; nt++) {
        const int p = nb + nt * 8 + 2 * tid4;
        float v0 = acc[nt][0] + bo0, v1 = acc[nt][1] + bo0;
        float v2 = acc[nt][2] + bo1, v3 = acc[nt][3] + bo1;
        if (r0 >= 18) { v0 = 1.f / (1.f + expf(-v0)); v1 = 1.f / (1.f + expf(-v1)); }
        if (r1 >= 18) { v2 = 1.f / (1.f + expf(-v2)); v3 = 1.f / (1.f + expf(-v3)); }
        omb[(long)p * 28 + r0]       = v0;
        omb[(long)(p + 1) * 28 + r0] = v1;
        if (r1 < 27) {
            omb[(long)p * 28 + r1]       = v2;
            omb[(long)(p + 1) * 28 + r1] = v3;
        }
    }
}

// ---------------------------------------------------------------------------
// Kernel 2: deformable conv via mma.sync fp16 2-product (R6 tiling).
// Warp w: o-stripe [16w,16w+16) x all 128 px. VSTRIDE=74 (37 u32, odd ->
// STS conflict-free, mma B loads 2-way instead of R6's 8-way).
// ---------------------------------------------------------------------------
#define VSTRIDE 74

__global__ __launch_bounds__(256, 2) void k_deform_mma(
    const float* __restrict__ x, const float* __restrict__ bias,
    float* __restrict__ out)
{
    __shared__ __align__(16) __half vsh[128 * VSTRIDE];
    __shared__ float cw[4][128];
    __shared__ int   cof[4][128];

    const int t    = threadIdx.x;
    const int lane = t & 31;
    const int wid  = t >> 5;
    const int gid  = lane >> 2;
    const int tid4 = lane & 3;
    const int y    = blockIdx.x;
    const int b    = blockIdx.y;

    const float* xb = x + b * (C_ * HW_);
    uint32_t* vshu = (uint32_t*)vsh;

    float acc[16][4];
#pragma unroll
    for (int pt = 0; pt < 16; pt++)
#pragma unroll
        for (int q = 0; q < 4; q++) acc[pt][q] = 0.f;

    for (int k = 0; k < 9; k++) {
        // --- per-pixel coords: clamped corners + mask-premultiplied weights ---
        if (t < 128) {
            const int p = t;
            const float* omp = g_om + ((long)((b * H_ + y) * W_) + p) * 28;
            float dy = omp[2 * k], dx = omp[2 * k + 1], m = omp[18 + k];
            float py  = (float)(y + k / 3 - 1) + dy;
            float pxf = (float)(p + k % 3 - 1) + dx;
            float fy = floorf(py), fx = floorf(pxf);
            int iy = (int)fy, ix = (int)fx;
            float wy = py - fy, wx = pxf - fx;
            int iy1 = iy + 1, ix1 = ix + 1;
            bool vy0 = (iy  >= 0) & (iy  < H_);
            bool vy1 = (iy1 >= 0) & (iy1 < H_);
            bool vx0 = (ix  >= 0) & (ix  < W_);
            bool vx1 = (ix1 >= 0) & (ix1 < W_);
            int cy0 = min(max(iy,  0), H_ - 1), cy1 = min(max(iy1, 0), H_ - 1);
            int cx0 = min(max(ix,  0), W_ - 1), cx1 = min(max(ix1, 0), W_ - 1);
            cof[0][p] = cy0 * W_ + cx0;
            cof[1][p] = cy0 * W_ + cx1;
            cof[2][p] = cy1 * W_ + cx0;
            cof[3][p] = cy1 * W_ + cx1;
            cw[0][p] = (vy0 & vx0) ? (1.f - wy) * (1.f - wx) * m : 0.f;
            cw[1][p] = (vy0 & vx1) ? (1.f - wy) * wx         * m : 0.f;
            cw[2][p] = (vy1 & vx0) ? wy         * (1.f - wx) * m : 0.f;
            cw[3][p] = (vy1 & vx1) ? wy         * wx         * m : 0.f;
        }
        __syncthreads();

        // --- gather: thread = (pixel, 32-ch half); fp32 bilinear -> fp16 ---
        {
            const int p  = t & 127;
            const int c0 = (t >> 7) * 32;
            const int o00 = cof[0][p], o01 = cof[1][p];
            const int o10 = cof[2][p], o11 = cof[3][p];
            const float w00 = cw[0][p], w01 = cw[1][p];
            const float w10 = cw[2][p], w11 = cw[3][p];
            const float* pc = xb + (c0 << 14);
            uint32_t* bh = vshu + p * (VSTRIDE / 2) + (c0 >> 1);
#pragma unroll 8
            for (int j = 0; j < 32; j += 2) {
                float v0 = fmaf(w00, pc[o00], fmaf(w01, pc[o01],
                           fmaf(w10, pc[o10], w11 * pc[o11])));
                const float* pc1 = pc + HW_;
                float v1 = fmaf(w00, pc1[o00], fmaf(w01, pc1[o01],
                           fmaf(w10, pc1[o10], w11 * pc1[o11])));
                bh[j >> 1] = f16x2(v0, v1);
                pc += 2 * HW_;
            }
        }
        __syncthreads();

        // --- mma: 2 products, K = 64 ch = 4 ksteps ---
        {
            const uint32_t* wf_h = g_wfrag + ((((k * 2 + 0) * 4) * 8 + wid) * 32 + lane) * 4;
            const uint32_t* wf_l = g_wfrag + ((((k * 2 + 1) * 4) * 8 + wid) * 32 + lane) * 4;
#pragma unroll
            for (int ks = 0; ks < 4; ks++) {
                uint4 ahv = *(const uint4*)(wf_h + ks * (8 * 32 * 4));
                uint4 alv = *(const uint4*)(wf_l + ks * (8 * 32 * 4));
                uint32_t ah[4] = {ahv.x, ahv.y, ahv.z, ahv.w};
                uint32_t al[4] = {alv.x, alv.y, alv.z, alv.w};
#pragma unroll
                for (int pt = 0; pt < 16; pt++) {
                    const int ad = (pt * 8 + gid) * (VSTRIDE / 2) + ks * 8 + tid4;
                    uint32_t b0 = vshu[ad];
                    uint32_t b1 = vshu[ad + 4];
                    mma_f16(acc[pt], ah, b0, b1);
                    mma_f16(acc[pt], al, b0, b1);
                }
            }
        }
        __syncthreads();
    }

    // --- epilogue: +bias, float2 stores ---
    const int o0 = wid * 16 + gid;
    const int o1 = o0 + 8;
    const float bo0 = bias[o0];
    const float bo1 = bias[o1];
    float* r0 = out + (((long)(b * O_ + o0) * H_ + y) << 7);
    float* r1 = out + (((long)(b * O_ + o1) * H_ + y) << 7);
#pragma unroll
    for (int pt = 0; pt < 16; pt++) {
        const int p = pt * 8 + 2 * tid4;
        float2 v0 = make_float2(acc[pt][0] + bo0, acc[pt][1] + bo0);
        float2 v1 = make_float2(acc[pt][2] + bo1, acc[pt][3] + bo1);
        *(float2*)(r0 + p) = v0;
        *(float2*)(r1 + p) = v1;
    }
}

// ---------------------------------------------------------------------------
extern "C" void kernel_launch(void* const* d_in, const int* in_sizes, int n_in,
                              void* d_out, int out_size)
{
    const float* input_feat = (const float*)d_in[0];  // [4,64,128,128]
    const float* inter      = (const float*)d_in[1];  // [4,64,128,128]
    const float* weight     = (const float*)d_in[2];  // [128,64,3,3]
    const float* bias       = (const float*)d_in[3];  // [128]
    const float* w_om       = (const float*)d_in[4];  // [27,128,3,3]
    const float* b_om       = (const float*)d_in[5];  // [27]
    float* out = (float*)d_out;                       // [4,128,128,128]

    k_prep<<<288, 256>>>(weight, w_om);
    k_prep_feat<<<4096, 256>>>(input_feat, inter);
    k_offconv_mma<<<dim3(128, 4), 256>>>(b_om);
    k_deform_mma<<<dim3(128, 4), 256>>>(input_feat, bias, out);
}